// round 14
// baseline (speedup 1.0000x reference)
#include <cuda_runtime.h>
#include <math.h>
#include <stdint.h>

// Problem constants
#define Bsz 8192
#define TILE_B 32
#define NBLK 256
#define THREADS 512

// Shared memory (float words), total 27220 (108,880 B) -> 2 blocks/SM
//  GEMM phase : AF [0,8192)  W double buffer [8192,24576) (2 x 8192, 16-d chunks)
//  overlay    : PA [0,8192)  TISC [8192,16384)  TMCI [16384,24576)
//  DOTSL [24576,25632) DOTSS [25632,26688)  RED at 26688+
#define OFF_AF    0
#define OFF_W     8192
#define WBUF      8192
#define OFF_PA    0
#define OFF_TISC  8192
#define OFF_TMCI  16384
#define OFF_DOTSL 24576
#define OFF_DOTSS 25632
#define OFF_REDP  26688
#define OFF_REDG  27200
#define OFF_FLAG  27216
#define SMEM_FLOATS 27220
#define SMEM_BYTES (SMEM_FLOATS * 4)

// Precomputed fragment tables (block-invariant; written by prep each call)
__device__ uint32_t gBW[131072];   // W frags: [kt 32][ntg 64][lane 32][reg 2]
__device__ uint32_t gTisc[8192];   // isc frags: [kt 32][ntc 4][lane 32][reg 2]
__device__ uint32_t gTmci[8192];   // mci frags
__device__ float g_c2[32];
__device__ float g_clsc[32];
__device__ float g_gaussPart[NBLK];
__device__ float g_piPart[NBLK * 32];
__device__ unsigned int g_count;

// ---- helpers ----
__device__ __forceinline__ uint32_t f2tf32(float f) {
    uint32_t r; asm("cvt.rna.tf32.f32 %0,%1;" : "=r"(r) : "f"(f)); return r;
}
__device__ __forceinline__ float wredsum(float v) {
#pragma unroll
    for (int o = 16; o; o >>= 1) v += __shfl_xor_sync(0xffffffffu, v, o);
    return v;
}
__device__ __forceinline__ void mma_tf32(float* d, const uint32_t* a,
                                         uint32_t b0, uint32_t b1) {
    asm volatile(
        "mma.sync.aligned.m16n8k8.row.col.f32.tf32.tf32.f32 "
        "{%0,%1,%2,%3},{%4,%5,%6,%7},{%8,%9},{%0,%1,%2,%3};"
        : "+f"(d[0]), "+f"(d[1]), "+f"(d[2]), "+f"(d[3])
        : "r"(a[0]), "r"(a[1]), "r"(a[2]), "r"(a[3]), "r"(b0), "r"(b1));
}
#define CP16(dst_u32, src_ptr) \
    asm volatile("cp.async.cg.shared.global [%0],[%1],16;" :: "r"(dst_u32), "l"(src_ptr))
#define CP_COMMIT() asm volatile("cp.async.commit_group;")
#define CP_WAIT(n)  asm volatile("cp.async.wait_group %0;" :: "n"(n))

// ---------------------------------------------------------------------------
// prep: W + cluster tables -> tf32 fragment order in global (proven layout)
// ---------------------------------------------------------------------------
__global__ void __launch_bounds__(1024)
prep_kernel(const float* __restrict__ Wmu, const float* __restrict__ Wsig,
            const float* __restrict__ muc, const float* __restrict__ lsc) {
    int b = blockIdx.x, t = threadIdx.x;
    if (b < 64) {
        int idx = b * 1024 + t;              // (kt*64 + ntg)*32 + lane
        int lane = idx & 31;
        int g = lane >> 2, tg = lane & 3;
        int ntg = (idx >> 5) & 63, kt = idx >> 11;
        const float* W = (ntg & 32) ? Wsig : Wmu;
        int e = (ntg & 31) * 8 + g;
        int d = kt * 8 + tg;
        uint2 vv = {f2tf32(W[e * 256 + d]), f2tf32(W[e * 256 + d + 4])};
        *(uint2*)&gBW[idx * 2] = vv;
    } else if (b < 68) {
        int idx = (b - 64) * 1024 + t;       // (kt*4 + ntc)*32 + lane
        int lane = idx & 31;
        int g = lane >> 2, tg = lane & 3;
        int ntc = (idx >> 5) & 3, kt = idx >> 7;
        int k = ntc * 8 + g;
        int d = kt * 8 + tg;
        float l0 = lsc[k * 256 + d], l1 = lsc[k * 256 + d + 4];
        float i0 = expf(-l0), i1 = expf(-l1);
        uint2 iv = {f2tf32(i0), f2tf32(i1)};
        uint2 mv = {f2tf32(muc[k * 256 + d] * i0), f2tf32(muc[k * 256 + d + 4] * i1)};
        *(uint2*)&gTisc[idx * 2] = iv;
        *(uint2*)&gTmci[idx * 2] = mv;
    } else {
        int k = t >> 5, lane = t & 31;       // warp per cluster
        float c2 = 0.f, cl = 0.f;
#pragma unroll
        for (int j = 0; j < 8; ++j) {
            int d = j * 32 + lane;
            float l = lsc[k * 256 + d];
            float iv = expf(-l);
            float mc = muc[k * 256 + d];
            c2 = fmaf(mc * mc, iv, c2);
            cl += l;
        }
        c2 = wredsum(c2);
        cl = wredsum(cl);
        if (lane == 0) { g_c2[k] = c2; g_clsc[k] = cl; }
    }
}

// ---- Phase-B epilogue -> PA (one 32x256 tf32 A matrix), MODE selects value
//      0: z^2 (+ writes z to out)   1: z   2: q = mu^2+exp(ls)   3: mu
template<int MODE>
__device__ __forceinline__ void build_pa(
    const float (&acc)[2][2][2][4], const float* __restrict__ EPS,
    const float* __restrict__ bmu, const float* __restrict__ bsig,
    float* __restrict__ out, uint32_t* smU, int b0, int wi, int lane) {
    int g = lane >> 2, tg = lane & 3, cb = wi * 16;
#pragma unroll
    for (int mt = 0; mt < 2; ++mt) {
#pragma unroll
        for (int j = 0; j < 2; ++j) {
            int e2 = cb + j * 8 + 2 * tg;
            float2 bm = *(const float2*)&bmu[e2];
            float2 bs = *(const float2*)&bsig[e2];
            int ktw = wi * 2 + j;
#pragma unroll
            for (int hi = 0; hi < 2; ++hi) {
                int r = mt * 16 + g + 8 * hi;
                int ci = hi * 2;
                float mu0 = acc[mt][0][j][ci + 0] + bm.x;
                float mu1 = acc[mt][0][j][ci + 1] + bm.y;
                float v0, v1;
                if (MODE == 3) { v0 = mu0; v1 = mu1; }
                else {
                    float ls0 = acc[mt][1][j][ci + 0] + bs.x;
                    float ls1 = acc[mt][1][j][ci + 1] + bs.y;
                    float ez0 = __expf(ls0), ez1 = __expf(ls1);
                    if (MODE == 2) { v0 = fmaf(mu0, mu0, ez0); v1 = fmaf(mu1, mu1, ez1); }
                    else {
                        float2 ep = *(const float2*)&EPS[(b0 + r) * 256 + e2];
                        float z0 = fmaf(sqrtf(ez0), ep.x, mu0);
                        float z1 = fmaf(sqrtf(ez1), ep.y, mu1);
                        if (MODE == 0) {
                            float2 zv = {z0, z1};
                            *(float2*)&out[(b0 + r) * 256 + e2] = zv;
                            v0 = z0 * z0; v1 = z1 * z1;
                        } else { v0 = z0; v1 = z1; }
                    }
                }
#pragma unroll
                for (int par = 0; par < 2; ++par) {
                    int dd = 2 * tg + par;
                    int kh = dd >> 2, tgp = dd & 3;
                    int reg = hi + 2 * kh;
                    int lanep = g * 4 + tgp;
                    smU[OFF_PA + ((ktw * 2 + mt) * 4 + reg) * 32 + lanep]
                        = f2tf32(par ? v1 : v0);
                }
            }
        }
    }
}

// ---- Phase C mini-GEMM: PA(32x256) @ table(256x32) -> dots (8 active warps)
__device__ __forceinline__ void phasec_gemm(uint32_t* smU, float* dots,
                                            int tblOff, bool rmw,
                                            int wi, int lane) {
    if (wi >= 8) return;
    int g = lane >> 2, tg = lane & 3;
    int mtc = wi >> 2, ntc = wi & 3;
    float dA[4] = {0.f, 0.f, 0.f, 0.f};
#pragma unroll 4
    for (int kt = 0; kt < 32; ++kt) {
        uint32_t af[4];
#pragma unroll
        for (int rr = 0; rr < 4; ++rr)
            af[rr] = smU[OFF_PA + ((kt * 2 + mtc) * 4 + rr) * 32 + lane];
        uint2 bv = *(const uint2*)&smU[tblOff + ((kt * 4 + ntc) * 32 + lane) * 2];
        mma_tf32(dA, af, bv.x, bv.y);
    }
    int rloc = mtc * 16 + g;
#pragma unroll
    for (int hi = 0; hi < 2; ++hi)
#pragma unroll
        for (int par = 0; par < 2; ++par) {
            int r = rloc + 8 * hi;
            int k = ntc * 8 + 2 * tg + par;
            int idx = r * 33 + k;
            float v = dA[hi * 2 + par];
            dots[idx] = rmw ? (dots[idx] - 2.f * v) : v;
        }
}

// ---------------------------------------------------------------------------
__global__ void __launch_bounds__(THREADS, 2)
fused_kernel(const float* __restrict__ X, const float* __restrict__ EPS,
             const float* __restrict__ bmu, const float* __restrict__ bsig,
             float* __restrict__ out, int out_size) {
    extern __shared__ float sm[];
    uint32_t* smU = (uint32_t*)sm;
    float* dotsL = sm + OFF_DOTSL;
    float* dotsS = sm + OFF_DOTSS;
    float* redPi = sm + OFF_REDP;
    float* redG  = sm + OFF_REDG;
    int*   flag  = (int*)(sm + OFF_FLAG);
    const uint32_t smBase = (uint32_t)__cvta_generic_to_shared(sm);

    const int t = threadIdx.x;
    const int b0 = blockIdx.x * TILE_B;
    const int wi = t >> 5, lane = t & 31;

    // ---- issue W chunk 0 copy (16 d = 32768 B) ----
    {
        uint32_t dst = smBase + OFF_W * 4;
        const char* src = (const char*)gBW;
#pragma unroll
        for (int p = 0; p < 4; ++p) {
            int off = (p * THREADS + t) * 16;
            CP16(dst + off, src + off);
        }
        CP_COMMIT();
    }

    // ============ X -> A fragments (tf32), 32 rows ============
#pragma unroll
    for (int p = 0; p < 16; ++p) {
        int i = p * THREADS + t;
        int r = i >> 8, d = i & 255;
        uint32_t v = f2tf32(X[(b0 + r) * 256 + d]);
        int mt = r >> 4, rl = r & 15, gg = rl & 7, hi = rl >> 3;
        int kt = d >> 3, dc = d & 7, tgx = dc & 3, kh = dc >> 2;
        smU[OFF_AF + (((kt * 2 + mt) * 32) + gg * 4 + tgx) * 4 + (hi + 2 * kh)] = v;
    }

    float acc[2][2][2][4];   // [mt][m][j][creg]
#pragma unroll
    for (int a = 0; a < 2; ++a)
#pragma unroll
        for (int b = 0; b < 2; ++b)
#pragma unroll
            for (int c = 0; c < 2; ++c)
#pragma unroll
                for (int q = 0; q < 4; ++q) acc[a][b][c][q] = 0.f;

    // ============ main GEMM: 16 chunks of 16 d, double-buffered ============
#pragma unroll 1
    for (int ch = 0; ch < 16; ++ch) {
        if (ch < 15) {
            uint32_t dst = smBase + (OFF_W + ((ch + 1) & 1) * WBUF) * 4;
            const char* src = (const char*)gBW + (size_t)(ch + 1) * 32768;
#pragma unroll
            for (int p = 0; p < 4; ++p) {
                int off = (p * THREADS + t) * 16;
                CP16(dst + off, src + off);
            }
            CP_COMMIT();
            CP_WAIT(1);
        } else {
            CP_WAIT(0);
        }
        __syncthreads();   // chunk ch visible (covers AF on ch=0)

        const uint32_t* bufW = smU + OFF_W + (ch & 1) * WBUF;
#pragma unroll
        for (int ktc = 0; ktc < 2; ++ktc) {
            int kt = ch * 2 + ktc;
            uint32_t a0[4], a1[4];
            *(uint4*)a0 = *(const uint4*)&smU[OFF_AF + ((kt * 2 + 0) * 32 + lane) * 4];
            *(uint4*)a1 = *(const uint4*)&smU[OFF_AF + ((kt * 2 + 1) * 32 + lane) * 4];
            uint2 bv[2][2];
#pragma unroll
            for (int m = 0; m < 2; ++m)
#pragma unroll
                for (int j = 0; j < 2; ++j) {
                    int ntg = m * 32 + wi * 2 + j;
                    bv[m][j] = *(const uint2*)&bufW[((ktc * 64 + ntg) * 32 + lane) * 2];
                }
#pragma unroll
            for (int m = 0; m < 2; ++m)
#pragma unroll
                for (int j = 0; j < 2; ++j) {
                    mma_tf32(acc[0][m][j], a0, bv[m][j].x, bv[m][j].y);
                    mma_tf32(acc[1][m][j], a1, bv[m][j].x, bv[m][j].y);
                }
        }
        if (ch < 15) __syncthreads();
    }
    __syncthreads();   // GEMM reads complete; overlays safe

    // ---- stage both cluster tables into dead W space ----
    {
        uint32_t dI = smBase + OFF_TISC * 4;
        uint32_t dM = smBase + OFF_TMCI * 4;
#pragma unroll
        for (int p = 0; p < 4; ++p) {
            int off = (p * THREADS + t) * 16;
            CP16(dI + off, (const char*)gTisc + off);
            CP16(dM + off, (const char*)gTmci + off);
        }
        CP_COMMIT();
    }

    // ============ Phase B/C: 4 passes ============
    build_pa<0>(acc, EPS, bmu, bsig, out, smU, b0, wi, lane);   // z^2 (+z out)
    CP_WAIT(0);
    __syncthreads();
    phasec_gemm(smU, dotsL, OFF_TISC, false, wi, lane);         // a1
    __syncthreads();

    build_pa<1>(acc, EPS, bmu, bsig, out, smU, b0, wi, lane);   // z
    __syncthreads();
    phasec_gemm(smU, dotsL, OFF_TMCI, true, wi, lane);          // a1 - 2 a2
    __syncthreads();

    build_pa<2>(acc, EPS, bmu, bsig, out, smU, b0, wi, lane);   // q
    __syncthreads();
    phasec_gemm(smU, dotsS, OFF_TISC, false, wi, lane);         // a3
    __syncthreads();

    build_pa<3>(acc, EPS, bmu, bsig, out, smU, b0, wi, lane);   // mu
    __syncthreads();
    phasec_gemm(smU, dotsS, OFF_TMCI, true, wi, lane);          // a3 - 2 a4
    __syncthreads();

    // ============ softmax + loss partials: warp per 2 rows, lane == k ======
    float c2v = g_c2[lane], clv = g_clsc[lane];
    float piAcc = 0.f, gAcc = 0.f;
#pragma unroll
    for (int rr = 0; rr < 2; ++rr) {
        int r = wi * 2 + rr;
        float logit = -(dotsL[r * 33 + lane] + c2v);
        float S = clv + dotsS[r * 33 + lane] + c2v;

        float mx = logit;
#pragma unroll
        for (int o = 16; o; o >>= 1) mx = fmaxf(mx, __shfl_xor_sync(0xffffffffu, mx, o));
        float p = __expf(logit - mx);
        float ssum = wredsum(p);
        float pi = p / ssum + 1e-10f;

        piAcc += pi;
        gAcc += wredsum(pi * S);
    }

    // ---- block partials ----
    redPi[wi * 32 + lane] = piAcc;
    if (lane == 0) redG[wi] = gAcc;
    __syncthreads();
    if (wi == 0) {
        float ps = 0.f;
#pragma unroll
        for (int i = 0; i < 16; ++i) ps += redPi[i * 32 + lane];
        g_piPart[blockIdx.x * 32 + lane] = ps;
        if (lane == 0) {
            float gsum = 0.f;
#pragma unroll
            for (int i = 0; i < 16; ++i) gsum += redG[i];
            g_gaussPart[blockIdx.x] = gsum;
        }
    }
    __syncthreads();

    // ---- last-block folded finalize ----
    if (t == 0) {
        __threadfence();
        unsigned int old = atomicAdd(&g_count, 1u);
        *flag = (old == NBLK - 1) ? 1 : 0;
    }
    __syncthreads();
    if (*flag) {
        if (t == 0) atomicExch(&g_count, 0u);
        __threadfence();
        if (t < 256) {
            float gg = g_gaussPart[t];
            gg = wredsum(gg);
            if (lane == 0) redG[wi] = gg;
        }
        {
            float ps = 0.f;
#pragma unroll
            for (int j = 0; j < 16; ++j)
                ps += g_piPart[(wi * 16 + j) * 32 + lane];
            redPi[wi * 32 + lane] = ps;
        }
        __syncthreads();
        if (t == 0) {
            float G = 0.f;
#pragma unroll
            for (int i = 0; i < 8; ++i) G += redG[i];
            out[out_size - 2] = 0.5f * G;
        }
        if (wi == 0) {
            float P = 0.f;
#pragma unroll
            for (int i = 0; i < 16; ++i) P += redPi[i * 32 + lane];
            float mp = P / (float)Bsz;
            float u = mp * logf(mp);
            u = wredsum(u);
            if (lane == 0) out[out_size - 1] = u / 32.0f;
        }
    }
}

// ---------------------------------------------------------------------------
extern "C" void kernel_launch(void* const* d_in, const int* in_sizes, int n_in,
                              void* d_out, int out_size) {
    const float* X    = (const float*)d_in[0];
    const float* EPS  = (const float*)d_in[1];
    const float* Wmu  = (const float*)d_in[2];
    const float* bmu  = (const float*)d_in[3];
    const float* Wsig = (const float*)d_in[4];
    const float* bsig = (const float*)d_in[5];
    const float* muc  = (const float*)d_in[6];
    const float* lsc  = (const float*)d_in[7];
    float* out = (float*)d_out;

    static bool attr_set = false;
    if (!attr_set) {
        cudaFuncSetAttribute(fused_kernel,
                             cudaFuncAttributeMaxDynamicSharedMemorySize, SMEM_BYTES);
        attr_set = true;
    }
    prep_kernel<<<69, 1024>>>(Wmu, Wsig, muc, lsc);
    fused_kernel<<<NBLK, THREADS, SMEM_BYTES>>>(X, EPS, bmu, bsig, out, out_size);
}

// round 15
// speedup vs baseline: 1.0322x; 1.0322x over previous
#include <cuda_runtime.h>
#include <math.h>
#include <stdint.h>

// Problem constants
#define Bsz 8192
#define TILE_B 64
#define NBLK 128
#define THREADS 1024

// Shared memory (float words) — same 230.4 KB footprint as R13
//  GEMM phase : AF [0,16384)  W double buffer [16384,49152) (2 x 16384)
//  overlay    : PA [0,32768)  TISC [32768,40960) TMCI [40960,49152)
//  DOTS [49152,57600) ([4][64 r][33]);  RED overlays DOTS post-softmax
#define OFF_AF   0
#define OFF_W    16384
#define BUFSTR   16384
#define OFF_PA   0
#define OFF_TISC 32768
#define OFF_TMCI 40960
#define OFF_DOTS 49152
#define OFF_REDP 49152
#define OFF_REDG 50176
#define OFF_FLAG 50208
#define SMEM_FLOATS 57600
#define SMEM_BYTES (SMEM_FLOATS * 4)

// Precomputed fragment tables (block-invariant; written by prep each call)
__device__ uint32_t gBW[131072];   // W frags: [kt 32][ntg 64][lane 32][reg 2]
__device__ uint32_t gTisc[8192];   // isc frags: [kt 32][ntc 4][lane 32][reg 2]
__device__ uint32_t gTmci[8192];   // mci frags
__device__ float g_c2[32];
__device__ float g_clsc[32];
__device__ float g_gaussPart[NBLK];
__device__ float g_piPart[NBLK * 32];
__device__ unsigned int g_count;

// ---- helpers ----
__device__ __forceinline__ uint32_t f2tf32(float f) {
    uint32_t r; asm("cvt.rna.tf32.f32 %0,%1;" : "=r"(r) : "f"(f)); return r;
}
__device__ __forceinline__ float wredsum(float v) {
#pragma unroll
    for (int o = 16; o; o >>= 1) v += __shfl_xor_sync(0xffffffffu, v, o);
    return v;
}
__device__ __forceinline__ void mma_tf32(float* d, const uint32_t* a,
                                         uint32_t b0, uint32_t b1) {
    asm volatile(
        "mma.sync.aligned.m16n8k8.row.col.f32.tf32.tf32.f32 "
        "{%0,%1,%2,%3},{%4,%5,%6,%7},{%8,%9},{%0,%1,%2,%3};"
        : "+f"(d[0]), "+f"(d[1]), "+f"(d[2]), "+f"(d[3])
        : "r"(a[0]), "r"(a[1]), "r"(a[2]), "r"(a[3]), "r"(b0), "r"(b1));
}
#define CP16(dst_u32, src_ptr) \
    asm volatile("cp.async.cg.shared.global [%0],[%1],16;" :: "r"(dst_u32), "l"(src_ptr))
#define CP_COMMIT() asm volatile("cp.async.commit_group;")
#define CP_WAIT(n)  asm volatile("cp.async.wait_group %0;" :: "n"(n))

// ---------------------------------------------------------------------------
// prep: W + cluster tables -> tf32 fragment order in global (proven layout)
// ---------------------------------------------------------------------------
__global__ void __launch_bounds__(1024)
prep_kernel(const float* __restrict__ Wmu, const float* __restrict__ Wsig,
            const float* __restrict__ muc, const float* __restrict__ lsc) {
    int b = blockIdx.x, t = threadIdx.x;
    if (b < 64) {
        int idx = b * 1024 + t;              // (kt*64 + ntg)*32 + lane
        int lane = idx & 31;
        int g = lane >> 2, tg = lane & 3;
        int ntg = (idx >> 5) & 63, kt = idx >> 11;
        const float* W = (ntg & 32) ? Wsig : Wmu;
        int e = (ntg & 31) * 8 + g;
        int d = kt * 8 + tg;
        uint2 vv = {f2tf32(W[e * 256 + d]), f2tf32(W[e * 256 + d + 4])};
        *(uint2*)&gBW[idx * 2] = vv;
    } else if (b < 68) {
        int idx = (b - 64) * 1024 + t;       // (kt*4 + ntc)*32 + lane
        int lane = idx & 31;
        int g = lane >> 2, tg = lane & 3;
        int ntc = (idx >> 5) & 3, kt = idx >> 7;
        int k = ntc * 8 + g;
        int d = kt * 8 + tg;
        float l0 = lsc[k * 256 + d], l1 = lsc[k * 256 + d + 4];
        float i0 = expf(-l0), i1 = expf(-l1);
        uint2 iv = {f2tf32(i0), f2tf32(i1)};
        uint2 mv = {f2tf32(muc[k * 256 + d] * i0), f2tf32(muc[k * 256 + d + 4] * i1)};
        *(uint2*)&gTisc[idx * 2] = iv;
        *(uint2*)&gTmci[idx * 2] = mv;
    } else {
        int k = t >> 5, lane = t & 31;       // warp per cluster
        float c2 = 0.f, cl = 0.f;
#pragma unroll
        for (int j = 0; j < 8; ++j) {
            int d = j * 32 + lane;
            float l = lsc[k * 256 + d];
            float iv = expf(-l);
            float mc = muc[k * 256 + d];
            c2 = fmaf(mc * mc, iv, c2);
            cl += l;
        }
        c2 = wredsum(c2);
        cl = wredsum(cl);
        if (lane == 0) { g_c2[k] = c2; g_clsc[k] = cl; }
    }
}

// ---------------------------------------------------------------------------
__global__ void __launch_bounds__(THREADS, 1)
fused_kernel(const float* __restrict__ X, const float* __restrict__ EPS,
             const float* __restrict__ bmu, const float* __restrict__ bsig,
             float* __restrict__ out, int out_size) {
    extern __shared__ float sm[];
    uint32_t* smU = (uint32_t*)sm;
    float* dots  = sm + OFF_DOTS;
    float* redPi = sm + OFF_REDP;
    float* redG  = sm + OFF_REDG;
    int*   flag  = (int*)(sm + OFF_FLAG);
    const uint32_t smBase = (uint32_t)__cvta_generic_to_shared(sm);

    const int t = threadIdx.x;
    const int b0 = blockIdx.x * TILE_B;
    const int wi = t >> 5, lane = t & 31;
    const int g = lane >> 2, tg = lane & 3;

    // ---- issue W chunk 0 copy (4 kt = 65536 B) ----
    {
        uint32_t dst = smBase + OFF_W * 4;
        const char* src = (const char*)gBW;
#pragma unroll
        for (int p = 0; p < 4; ++p) {
            int off = (p * THREADS + t) * 16;
            CP16(dst + off, src + off);
        }
        CP_COMMIT();
    }

    // ============ X -> A fragments (tf32), 64 rows ============
#pragma unroll
    for (int p = 0; p < 16; ++p) {
        int i = p * THREADS + t;
        int r = i >> 8, d = i & 255;
        uint32_t v = f2tf32(X[(b0 + r) * 256 + d]);
        int mt = r >> 4, rl = r & 15, gg = rl & 7, hi = rl >> 3;
        int kt = d >> 3, dc = d & 7, tgx = dc & 3, kh = dc >> 2;
        smU[OFF_AF + (((kt * 4 + mt) * 32) + gg * 4 + tgx) * 4 + (hi + 2 * kh)] = v;
    }

    float acc[4][2][4];   // [mt][mat: 0=mu 1=sig][creg]
#pragma unroll
    for (int a = 0; a < 4; ++a)
#pragma unroll
        for (int b = 0; b < 2; ++b)
#pragma unroll
            for (int q = 0; q < 4; ++q) acc[a][b][q] = 0.f;

    // ============ main GEMM: 8 chunks of 4 kt, double-buffered ============
#pragma unroll 1
    for (int ch = 0; ch < 8; ++ch) {
        if (ch < 7) {
            uint32_t dst = smBase + (OFF_W + ((ch + 1) & 1) * BUFSTR) * 4;
            const char* src = (const char*)gBW + (size_t)(ch + 1) * 65536;
#pragma unroll
            for (int p = 0; p < 4; ++p) {
                int off = (p * THREADS + t) * 16;
                CP16(dst + off, src + off);
            }
            CP_COMMIT();
            CP_WAIT(1);
        } else {
            CP_WAIT(0);
        }
        __syncthreads();   // chunk ch visible (covers AF on ch=0)

        const uint32_t* bufW = smU + OFF_W + (ch & 1) * BUFSTR;
#pragma unroll
        for (int ktc = 0; ktc < 4; ++ktc) {
            int kt = ch * 4 + ktc;
            uint2 bv0 = *(const uint2*)&bufW[((ktc * 64 + wi) * 32 + lane) * 2];
            uint2 bv1 = *(const uint2*)&bufW[((ktc * 64 + 32 + wi) * 32 + lane) * 2];
#pragma unroll
            for (int mt = 0; mt < 4; ++mt) {
                uint32_t a[4];
                *(uint4*)a = *(const uint4*)&smU[OFF_AF + ((kt * 4 + mt) * 32 + lane) * 4];
                mma_tf32(acc[mt][0], a, bv0.x, bv0.y);
                mma_tf32(acc[mt][1], a, bv1.x, bv1.y);
            }
        }
        if (ch < 7) __syncthreads();
    }
    __syncthreads();   // GEMM reads complete; overlays safe

    // ---- stage both cluster tables into dead W-buf 1 space ----
    {
        uint32_t dI = smBase + OFF_TISC * 4;
        uint32_t dM = smBase + OFF_TMCI * 4;
#pragma unroll
        for (int p = 0; p < 2; ++p) {
            int off = (p * THREADS + t) * 16;
            CP16(dI + off, (const char*)gTisc + off);
            CP16(dM + off, (const char*)gTmci + off);
        }
        CP_COMMIT();
    }

    // ============ Phase B pass 1: z out + PA = [z^2 ; q] ============
    {
        int e2 = wi * 8 + 2 * tg;
        float2 bm = *(const float2*)&bmu[e2];
        float2 bs = *(const float2*)&bsig[e2];
#pragma unroll
        for (int mt = 0; mt < 4; ++mt) {
#pragma unroll
            for (int hi = 0; hi < 2; ++hi) {
                int r = mt * 16 + g + 8 * hi;
                int ci = hi * 2;
                float mu0 = acc[mt][0][ci + 0] + bm.x;
                float mu1 = acc[mt][0][ci + 1] + bm.y;
                float ls0 = acc[mt][1][ci + 0] + bs.x;
                float ls1 = acc[mt][1][ci + 1] + bs.y;
                float ez0 = __expf(ls0), ez1 = __expf(ls1);
                float2 ep = *(const float2*)&EPS[(b0 + r) * 256 + e2];
                float z0 = fmaf(sqrtf(ez0), ep.x, mu0);
                float z1 = fmaf(sqrtf(ez1), ep.y, mu1);
                float2 zv = {z0, z1};
                *(float2*)&out[(b0 + r) * 256 + e2] = zv;
                float q0 = fmaf(mu0, mu0, ez0);
                float q1 = fmaf(mu1, mu1, ez1);
#pragma unroll
                for (int par = 0; par < 2; ++par) {
                    int dd = 2 * tg + par;
                    int kh = dd >> 2, tgp = dd & 3;
                    int reg = hi + 2 * kh;
                    int lanep = g * 4 + tgp;
                    float zz = par ? z1 : z0;
                    float qq = par ? q1 : q0;
                    smU[OFF_PA + ((wi * 8 + mt) * 4 + reg) * 32 + lanep]     = f2tf32(zz * zz);
                    smU[OFF_PA + ((wi * 8 + mt + 4) * 4 + reg) * 32 + lanep] = f2tf32(qq);
                }
            }
        }
    }
    CP_WAIT(0);
    __syncthreads();   // PA + tables ready

    const int mtc = wi >> 2;          // 0..7 (16-row tile of 128-row PA)
    const int ntc = wi & 3;           // k quarter

    // ============ Phase C GEMM 1: [z^2;q] @ isc -> a1, a3 ============
    {
        float dA[4] = {0.f, 0.f, 0.f, 0.f};
#pragma unroll 4
        for (int kt = 0; kt < 32; ++kt) {
            uint32_t af[4];
#pragma unroll
            for (int rr = 0; rr < 4; ++rr)
                af[rr] = smU[OFF_PA + ((kt * 8 + mtc) * 4 + rr) * 32 + lane];
            uint2 iv = *(const uint2*)&smU[OFF_TISC + ((kt * 4 + ntc) * 32 + lane) * 2];
            mma_tf32(dA, af, iv.x, iv.y);
        }
        int dot = (mtc < 4) ? 0 : 2;
        int rloc = (mtc & 3) * 16 + g;
#pragma unroll
        for (int hi = 0; hi < 2; ++hi)
#pragma unroll
            for (int par = 0; par < 2; ++par) {
                int r = rloc + 8 * hi;
                int k = ntc * 8 + 2 * tg + par;
                dots[dot * 2112 + r * 33 + k] = dA[hi * 2 + par];
            }
    }
    __syncthreads();   // GEMM1 PA reads done; PA rebuild safe

    // ============ Phase B pass 2: PA = [z ; mu] (recomputed) ============
    {
        int e2 = wi * 8 + 2 * tg;
        float2 bm = *(const float2*)&bmu[e2];
        float2 bs = *(const float2*)&bsig[e2];
#pragma unroll
        for (int mt = 0; mt < 4; ++mt) {
#pragma unroll
            for (int hi = 0; hi < 2; ++hi) {
                int r = mt * 16 + g + 8 * hi;
                int ci = hi * 2;
                float mu0 = acc[mt][0][ci + 0] + bm.x;
                float mu1 = acc[mt][0][ci + 1] + bm.y;
                float ls0 = acc[mt][1][ci + 0] + bs.x;
                float ls1 = acc[mt][1][ci + 1] + bs.y;
                float2 ep = *(const float2*)&EPS[(b0 + r) * 256 + e2];
                float z0 = fmaf(sqrtf(__expf(ls0)), ep.x, mu0);
                float z1 = fmaf(sqrtf(__expf(ls1)), ep.y, mu1);
#pragma unroll
                for (int par = 0; par < 2; ++par) {
                    int dd = 2 * tg + par;
                    int kh = dd >> 2, tgp = dd & 3;
                    int reg = hi + 2 * kh;
                    int lanep = g * 4 + tgp;
                    float zz = par ? z1 : z0;
                    float mm = par ? mu1 : mu0;
                    smU[OFF_PA + ((wi * 8 + mt) * 4 + reg) * 32 + lanep]     = f2tf32(zz);
                    smU[OFF_PA + ((wi * 8 + mt + 4) * 4 + reg) * 32 + lanep] = f2tf32(mm);
                }
            }
        }
    }
    __syncthreads();

    // ============ Phase C GEMM 2: [z;mu] @ mci -> a2, a4 ============
    {
        float dA[4] = {0.f, 0.f, 0.f, 0.f};
#pragma unroll 4
        for (int kt = 0; kt < 32; ++kt) {
            uint32_t af[4];
#pragma unroll
            for (int rr = 0; rr < 4; ++rr)
                af[rr] = smU[OFF_PA + ((kt * 8 + mtc) * 4 + rr) * 32 + lane];
            uint2 mv = *(const uint2*)&smU[OFF_TMCI + ((kt * 4 + ntc) * 32 + lane) * 2];
            mma_tf32(dA, af, mv.x, mv.y);
        }
        int dot = (mtc < 4) ? 1 : 3;
        int rloc = (mtc & 3) * 16 + g;
#pragma unroll
        for (int hi = 0; hi < 2; ++hi)
#pragma unroll
            for (int par = 0; par < 2; ++par) {
                int r = rloc + 8 * hi;
                int k = ntc * 8 + 2 * tg + par;
                dots[dot * 2112 + r * 33 + k] = dA[hi * 2 + par];
            }
    }
    __syncthreads();

    // ============ softmax + loss partials: warp per 2 rows, lane == k ======
    float c2v = g_c2[lane], clv = g_clsc[lane];
    float piAcc = 0.f, gAcc = 0.f;
#pragma unroll
    for (int rr = 0; rr < 2; ++rr) {
        int r = wi * 2 + rr;
        float a1 = dots[0 * 2112 + r * 33 + lane];
        float a2 = dots[1 * 2112 + r * 33 + lane];
        float a3 = dots[2 * 2112 + r * 33 + lane];
        float a4 = dots[3 * 2112 + r * 33 + lane];

        float logit = -(a1 - 2.f * a2 + c2v);
        float S = clv + a3 - 2.f * a4 + c2v;

        float mx = logit;
#pragma unroll
        for (int o = 16; o; o >>= 1) mx = fmaxf(mx, __shfl_xor_sync(0xffffffffu, mx, o));
        float p = __expf(logit - mx);
        float ssum = wredsum(p);
        float pi = p / ssum + 1e-10f;

        piAcc += pi;
        gAcc += wredsum(pi * S);
    }
    __syncthreads();   // all dots reads done; RED overlay safe

    // ---- block partials (32 warps) ----
    redPi[wi * 32 + lane] = piAcc;
    if (lane == 0) redG[wi] = gAcc;
    __syncthreads();
    if (wi == 0) {
        float ps = 0.f;
#pragma unroll
        for (int i = 0; i < 32; ++i) ps += redPi[i * 32 + lane];
        g_piPart[blockIdx.x * 32 + lane] = ps;
        if (lane == 0) {
            float gsum = 0.f;
#pragma unroll
            for (int i = 0; i < 32; ++i) gsum += redG[i];
            g_gaussPart[blockIdx.x] = gsum;
        }
    }
    __syncthreads();

    // ---- last-block folded finalize ----
    if (t == 0) {
        __threadfence();
        unsigned int old = atomicAdd(&g_count, 1u);
        *flag = (old == NBLK - 1) ? 1 : 0;
    }
    __syncthreads();
    if (*flag) {
        if (t == 0) atomicExch(&g_count, 0u);
        __threadfence();
        if (t < NBLK) {
            float gg = g_gaussPart[t];
            gg = wredsum(gg);
            if (lane == 0) redG[wi] = gg;
        }
        {
            float ps = 0.f;
#pragma unroll
            for (int j = 0; j < 4; ++j)
                ps += g_piPart[(wi * 4 + j) * 32 + lane];
            redPi[wi * 32 + lane] = ps;
        }
        __syncthreads();
        if (t == 0) {
            float G = 0.f;
#pragma unroll
            for (int i = 0; i < 4; ++i) G += redG[i];
            out[out_size - 2] = 0.5f * G;
        }
        if (wi == 0) {
            float P = 0.f;
#pragma unroll
            for (int i = 0; i < 32; ++i) P += redPi[i * 32 + lane];
            float mp = P / (float)Bsz;
            float u = mp * logf(mp);
            u = wredsum(u);
            if (lane == 0) out[out_size - 1] = u / 32.0f;
        }
    }
}

// ---------------------------------------------------------------------------
extern "C" void kernel_launch(void* const* d_in, const int* in_sizes, int n_in,
                              void* d_out, int out_size) {
    const float* X    = (const float*)d_in[0];
    const float* EPS  = (const float*)d_in[1];
    const float* Wmu  = (const float*)d_in[2];
    const float* bmu  = (const float*)d_in[3];
    const float* Wsig = (const float*)d_in[4];
    const float* bsig = (const float*)d_in[5];
    const float* muc  = (const float*)d_in[6];
    const float* lsc  = (const float*)d_in[7];
    float* out = (float*)d_out;

    static bool attr_set = false;
    if (!attr_set) {
        cudaFuncSetAttribute(fused_kernel,
                             cudaFuncAttributeMaxDynamicSharedMemorySize, SMEM_BYTES);
        attr_set = true;
    }
    prep_kernel<<<69, 1024>>>(Wmu, Wsig, muc, lsc);
    fused_kernel<<<NBLK, THREADS, SMEM_BYTES>>>(X, EPS, bmu, bsig, out, out_size);
}

// round 16
// speedup vs baseline: 1.2303x; 1.1920x over previous
#include <cuda_runtime.h>
#include <math.h>
#include <stdint.h>

// Problem constants
#define Bsz 8192
#define TILE_B 64
#define NBLK 128
#define THREADS 512

// Shared memory (float words) — same 230.4 KB footprint as R13
//  GEMM phase : AF [0,16384)  W double buffer [16384,49152) (2 x 16384)
//               (W buffer sliced per-warp: warp wi owns [wi*1024, wi*1024+1024))
//  overlay    : PA [0,32768)  TISC [32768,40960) TMCI [40960,49152)
//  DOTS [49152,57600) ([4][64 r][33]);  RED overlays DOTS post-softmax
#define OFF_AF   0
#define OFF_W    16384
#define BUFSTR   16384
#define OFF_PA   0
#define OFF_TISC 32768
#define OFF_TMCI 40960
#define OFF_DOTS 49152
#define OFF_REDP 49152
#define OFF_REDG 49664
#define OFF_FLAG 49680
#define SMEM_FLOATS 57600
#define SMEM_BYTES (SMEM_FLOATS * 4)

// Precomputed fragment tables (block-invariant; written by prep each call)
// gBW layout: [ch 8][wi 16][ktc 4][ntgl 4][lane 32][reg 2]  (warp-sliced chunks)
__device__ uint32_t gBW[131072];
__device__ uint32_t gTisc[8192];   // isc frags: [kt 32][ntc 4][lane 32][reg 2]
__device__ uint32_t gTmci[8192];   // mci frags
__device__ float g_c2[32];
__device__ float g_clsc[32];
__device__ float g_gaussPart[NBLK];
__device__ float g_piPart[NBLK * 32];
__device__ unsigned int g_count;

// ---- helpers ----
__device__ __forceinline__ uint32_t f2tf32(float f) {
    uint32_t r; asm("cvt.rna.tf32.f32 %0,%1;" : "=r"(r) : "f"(f)); return r;
}
__device__ __forceinline__ float wredsum(float v) {
#pragma unroll
    for (int o = 16; o; o >>= 1) v += __shfl_xor_sync(0xffffffffu, v, o);
    return v;
}
__device__ __forceinline__ void mma_tf32(float* d, const uint32_t* a,
                                         uint32_t b0, uint32_t b1) {
    asm volatile(
        "mma.sync.aligned.m16n8k8.row.col.f32.tf32.tf32.f32 "
        "{%0,%1,%2,%3},{%4,%5,%6,%7},{%8,%9},{%0,%1,%2,%3};"
        : "+f"(d[0]), "+f"(d[1]), "+f"(d[2]), "+f"(d[3])
        : "r"(a[0]), "r"(a[1]), "r"(a[2]), "r"(a[3]), "r"(b0), "r"(b1));
}
#define CP16(dst_u32, src_ptr) \
    asm volatile("cp.async.cg.shared.global [%0],[%1],16;" :: "r"(dst_u32), "l"(src_ptr))
#define CP_COMMIT() asm volatile("cp.async.commit_group;")
#define CP_WAIT(n)  asm volatile("cp.async.wait_group %0;" :: "n"(n))

// ---------------------------------------------------------------------------
// prep: W + cluster tables -> tf32 fragment order in global
// gBW now warp-sliced: value mapping identical to R13, address remapped.
// ---------------------------------------------------------------------------
__global__ void __launch_bounds__(1024)
prep_kernel(const float* __restrict__ Wmu, const float* __restrict__ Wsig,
            const float* __restrict__ muc, const float* __restrict__ lsc) {
    int b = blockIdx.x, t = threadIdx.x;
    if (b < 64) {
        int idx = b * 1024 + t;              // (kt*64 + ntg)*32 + lane
        int lane = idx & 31;
        int g = lane >> 2, tg = lane & 3;
        int ntg = (idx >> 5) & 63, kt = idx >> 11;
        const float* W = (ntg & 32) ? Wsig : Wmu;
        int e = (ntg & 31) * 8 + g;
        int d = kt * 8 + tg;
        uint2 vv = {f2tf32(W[e * 256 + d]), f2tf32(W[e * 256 + d + 4])};
        // remap: ch = kt>>2, ktc = kt&3, wi = (ntg&31)>>1, ntgl = ((ntg>>5)<<1)|(ntg&1)
        int ch = kt >> 2, ktc = kt & 3;
        int wiw = (ntg & 31) >> 1;
        int ntgl = ((ntg >> 5) << 1) | (ntg & 1);
        int nidx = (((ch * 16 + wiw) * 4 + ktc) * 4 + ntgl) * 32 + lane;
        *(uint2*)&gBW[nidx * 2] = vv;
    } else if (b < 68) {
        int idx = (b - 64) * 1024 + t;       // (kt*4 + ntc)*32 + lane
        int lane = idx & 31;
        int g = lane >> 2, tg = lane & 3;
        int ntc = (idx >> 5) & 3, kt = idx >> 7;
        int k = ntc * 8 + g;
        int d = kt * 8 + tg;
        float l0 = lsc[k * 256 + d], l1 = lsc[k * 256 + d + 4];
        float i0 = expf(-l0), i1 = expf(-l1);
        uint2 iv = {f2tf32(i0), f2tf32(i1)};
        uint2 mv = {f2tf32(muc[k * 256 + d] * i0), f2tf32(muc[k * 256 + d + 4] * i1)};
        *(uint2*)&gTisc[idx * 2] = iv;
        *(uint2*)&gTmci[idx * 2] = mv;
    } else {
        int k = t >> 5, lane = t & 31;       // warp per cluster
        float c2 = 0.f, cl = 0.f;
#pragma unroll
        for (int j = 0; j < 8; ++j) {
            int d = j * 32 + lane;
            float l = lsc[k * 256 + d];
            float iv = expf(-l);
            float mc = muc[k * 256 + d];
            c2 = fmaf(mc * mc, iv, c2);
            cl += l;
        }
        c2 = wredsum(c2);
        cl = wredsum(cl);
        if (lane == 0) { g_c2[k] = c2; g_clsc[k] = cl; }
    }
}

// ---------------------------------------------------------------------------
__global__ void __launch_bounds__(THREADS)
fused_kernel(const float* __restrict__ X, const float* __restrict__ EPS,
             const float* __restrict__ bmu, const float* __restrict__ bsig,
             float* __restrict__ out, int out_size) {
    extern __shared__ float sm[];
    uint32_t* smU = (uint32_t*)sm;
    float* dots  = sm + OFF_DOTS;
    float* redPi = sm + OFF_REDP;
    float* redG  = sm + OFF_REDG;
    int*   flag  = (int*)(sm + OFF_FLAG);
    const uint32_t smBase = (uint32_t)__cvta_generic_to_shared(sm);

    const int t = threadIdx.x;
    const int b0 = blockIdx.x * TILE_B;
    const int wi = t >> 5, lane = t & 31;
    const int g = lane >> 2, tg = lane & 3;
    const int cb = wi * 16;

    // warp-private W pipeline pointers
    const char* wsrc = (const char*)gBW + (size_t)wi * 4096;    // + ch*65536
    const int laneOff = lane * 16;

    // ---- issue warp's slice of W chunk 0 ----
    {
        uint32_t dst = smBase + (OFF_W + wi * 1024) * 4;
#pragma unroll
        for (int p = 0; p < 8; ++p)
            CP16(dst + p * 512 + laneOff, wsrc + p * 512 + laneOff);
        CP_COMMIT();
    }

    // ============ X -> A fragments (tf32), 64 rows ============
#pragma unroll
    for (int p = 0; p < 32; ++p) {
        int i = p * THREADS + t;
        int r = i >> 8, d = i & 255;
        uint32_t v = f2tf32(X[(b0 + r) * 256 + d]);
        int mt = r >> 4, rl = r & 15, gg = rl & 7, hi = rl >> 3;
        int kt = d >> 3, dc = d & 7, tgx = dc & 3, kh = dc >> 2;
        smU[OFF_AF + (((kt * 4 + mt) * 32) + gg * 4 + tgx) * 4 + (hi + 2 * kh)] = v;
    }

    float acc[4][2][2][4];   // [mt][m][j][creg]
#pragma unroll
    for (int a = 0; a < 4; ++a)
#pragma unroll
        for (int b = 0; b < 2; ++b)
#pragma unroll
            for (int c = 0; c < 2; ++c)
#pragma unroll
                for (int q = 0; q < 4; ++q) acc[a][b][c][q] = 0.f;

    __syncthreads();   // AF visible to all; after this, mainloop is barrier-free

    // ============ main GEMM: warp-private double-buffered pipelines ========
#pragma unroll 1
    for (int ch = 0; ch < 8; ++ch) {
        if (ch < 7) {
            uint32_t dst = smBase + (OFF_W + ((ch + 1) & 1) * BUFSTR + wi * 1024) * 4;
            const char* src = wsrc + (size_t)(ch + 1) * 65536;
#pragma unroll
            for (int p = 0; p < 8; ++p)
                CP16(dst + p * 512 + laneOff, src + p * 512 + laneOff);
            CP_COMMIT();
            CP_WAIT(1);
        } else {
            CP_WAIT(0);
        }
        __syncwarp();   // cross-lane visibility of this warp's staged slice

        const uint32_t* ws = smU + OFF_W + (ch & 1) * BUFSTR + wi * 1024;
#pragma unroll
        for (int ktc = 0; ktc < 4; ++ktc) {
            int kt = ch * 4 + ktc;
            uint32_t a[4][4];
#pragma unroll
            for (int mt = 0; mt < 4; ++mt)
                *(uint4*)a[mt] = *(const uint4*)&smU[OFF_AF + ((kt * 4 + mt) * 32 + lane) * 4];
            uint2 bv[2][2];
#pragma unroll
            for (int m = 0; m < 2; ++m)
#pragma unroll
                for (int j = 0; j < 2; ++j)
                    bv[m][j] = *(const uint2*)&ws[((ktc * 4 + m * 2 + j) * 32 + lane) * 2];
#pragma unroll
            for (int m = 0; m < 2; ++m)
#pragma unroll
                for (int j = 0; j < 2; ++j)
#pragma unroll
                    for (int mt = 0; mt < 4; ++mt)
                        mma_tf32(acc[mt][m][j], a[mt], bv[m][j].x, bv[m][j].y);
        }
    }
    __syncthreads();   // all warps done with AF/W; overlays safe

    // ---- issue both cluster-table copies (dead W-buf space) ----
    {
        uint32_t dI = smBase + OFF_TISC * 4;
        uint32_t dM = smBase + OFF_TMCI * 4;
#pragma unroll
        for (int p = 0; p < 4; ++p) {
            int off = (p * THREADS + t) * 16;
            CP16(dI + off, (const char*)gTisc + off);
            CP16(dM + off, (const char*)gTmci + off);
        }
        CP_COMMIT();
    }

    // ============ Phase B pass 1: z out + PA = [z^2 ; q] ============
#pragma unroll
    for (int mt = 0; mt < 4; ++mt) {
#pragma unroll
        for (int j = 0; j < 2; ++j) {
            int e2 = cb + j * 8 + 2 * tg;
            float2 bm = *(const float2*)&bmu[e2];
            float2 bs = *(const float2*)&bsig[e2];
            int ktw = wi * 2 + j;
#pragma unroll
            for (int hi = 0; hi < 2; ++hi) {
                int r = mt * 16 + g + 8 * hi;
                int ci = hi * 2;
                float mu0 = acc[mt][0][j][ci + 0] + bm.x;
                float mu1 = acc[mt][0][j][ci + 1] + bm.y;
                float ls0 = acc[mt][1][j][ci + 0] + bs.x;
                float ls1 = acc[mt][1][j][ci + 1] + bs.y;
                float ez0 = __expf(ls0), ez1 = __expf(ls1);
                float2 ep = *(const float2*)&EPS[(b0 + r) * 256 + e2];
                float z0 = fmaf(sqrtf(ez0), ep.x, mu0);
                float z1 = fmaf(sqrtf(ez1), ep.y, mu1);
                float2 zv = {z0, z1};
                *(float2*)&out[(b0 + r) * 256 + e2] = zv;
                float q0 = fmaf(mu0, mu0, ez0);
                float q1 = fmaf(mu1, mu1, ez1);
#pragma unroll
                for (int par = 0; par < 2; ++par) {
                    int dd = 2 * tg + par;
                    int kh = dd >> 2, tgp = dd & 3;
                    int reg = hi + 2 * kh;
                    int lanep = g * 4 + tgp;
                    float zz = par ? z1 : z0;
                    float qq = par ? q1 : q0;
                    smU[OFF_PA + ((ktw * 8 + mt) * 4 + reg) * 32 + lanep]     = f2tf32(zz * zz);
                    smU[OFF_PA + ((ktw * 8 + mt + 4) * 4 + reg) * 32 + lanep] = f2tf32(qq);
                }
            }
        }
    }
    CP_WAIT(0);
    __syncthreads();   // PA + tables ready

    const int mtc = wi >> 1;          // 0..7 -> 16-row tile
    const int ntch = wi & 1;          // k half

    // ============ Phase C GEMM 1: [z^2;q] @ isc -> a1, a3 ============
    {
        float dA[2][4];
#pragma unroll
        for (int s = 0; s < 2; ++s)
#pragma unroll
            for (int q = 0; q < 4; ++q) dA[s][q] = 0.f;
#pragma unroll 4
        for (int kt = 0; kt < 32; ++kt) {
            uint32_t af[4];
#pragma unroll
            for (int rr = 0; rr < 4; ++rr)
                af[rr] = smU[OFF_PA + ((kt * 8 + mtc) * 4 + rr) * 32 + lane];
#pragma unroll
            for (int s = 0; s < 2; ++s) {
                int ntc = ntch * 2 + s;
                uint2 iv = *(const uint2*)&smU[OFF_TISC + ((kt * 4 + ntc) * 32 + lane) * 2];
                mma_tf32(dA[s], af, iv.x, iv.y);
            }
        }
        int dot = (mtc < 4) ? 0 : 2;
        int rloc = (mtc & 3) * 16 + g;
#pragma unroll
        for (int s = 0; s < 2; ++s)
#pragma unroll
            for (int hi = 0; hi < 2; ++hi)
#pragma unroll
                for (int par = 0; par < 2; ++par) {
                    int r = rloc + 8 * hi;
                    int k = ntch * 16 + s * 8 + 2 * tg + par;
                    dots[dot * 2112 + r * 33 + k] = dA[s][hi * 2 + par];
                }
    }
    __syncthreads();   // GEMM1 PA reads done; PA rebuild safe

    // ============ Phase B pass 2: PA = [z ; mu] (recomputed) ============
#pragma unroll
    for (int mt = 0; mt < 4; ++mt) {
#pragma unroll
        for (int j = 0; j < 2; ++j) {
            int e2 = cb + j * 8 + 2 * tg;
            float2 bm = *(const float2*)&bmu[e2];
            float2 bs = *(const float2*)&bsig[e2];
            int ktw = wi * 2 + j;
#pragma unroll
            for (int hi = 0; hi < 2; ++hi) {
                int r = mt * 16 + g + 8 * hi;
                int ci = hi * 2;
                float mu0 = acc[mt][0][j][ci + 0] + bm.x;
                float mu1 = acc[mt][0][j][ci + 1] + bm.y;
                float ls0 = acc[mt][1][j][ci + 0] + bs.x;
                float ls1 = acc[mt][1][j][ci + 1] + bs.y;
                float2 ep = *(const float2*)&EPS[(b0 + r) * 256 + e2];
                float z0 = fmaf(sqrtf(__expf(ls0)), ep.x, mu0);
                float z1 = fmaf(sqrtf(__expf(ls1)), ep.y, mu1);
#pragma unroll
                for (int par = 0; par < 2; ++par) {
                    int dd = 2 * tg + par;
                    int kh = dd >> 2, tgp = dd & 3;
                    int reg = hi + 2 * kh;
                    int lanep = g * 4 + tgp;
                    float zz = par ? z1 : z0;
                    float mm = par ? mu1 : mu0;
                    smU[OFF_PA + ((ktw * 8 + mt) * 4 + reg) * 32 + lanep]     = f2tf32(zz);
                    smU[OFF_PA + ((ktw * 8 + mt + 4) * 4 + reg) * 32 + lanep] = f2tf32(mm);
                }
            }
        }
    }
    __syncthreads();

    // ============ Phase C GEMM 2: [z;mu] @ mci -> a2, a4 ============
    {
        float dA[2][4];
#pragma unroll
        for (int s = 0; s < 2; ++s)
#pragma unroll
            for (int q = 0; q < 4; ++q) dA[s][q] = 0.f;
#pragma unroll 4
        for (int kt = 0; kt < 32; ++kt) {
            uint32_t af[4];
#pragma unroll
            for (int rr = 0; rr < 4; ++rr)
                af[rr] = smU[OFF_PA + ((kt * 8 + mtc) * 4 + rr) * 32 + lane];
#pragma unroll
            for (int s = 0; s < 2; ++s) {
                int ntc = ntch * 2 + s;
                uint2 mv = *(const uint2*)&smU[OFF_TMCI + ((kt * 4 + ntc) * 32 + lane) * 2];
                mma_tf32(dA[s], af, mv.x, mv.y);
            }
        }
        int dot = (mtc < 4) ? 1 : 3;
        int rloc = (mtc & 3) * 16 + g;
#pragma unroll
        for (int s = 0; s < 2; ++s)
#pragma unroll
            for (int hi = 0; hi < 2; ++hi)
#pragma unroll
                for (int par = 0; par < 2; ++par) {
                    int r = rloc + 8 * hi;
                    int k = ntch * 16 + s * 8 + 2 * tg + par;
                    dots[dot * 2112 + r * 33 + k] = dA[s][hi * 2 + par];
                }
    }
    __syncthreads();

    // ============ softmax + loss partials: warp per 4 rows, lane == k ======
    float c2v = g_c2[lane], clv = g_clsc[lane];
    float piAcc = 0.f, gAcc = 0.f;
#pragma unroll
    for (int rr = 0; rr < 4; ++rr) {
        int r = wi * 4 + rr;
        float a1 = dots[0 * 2112 + r * 33 + lane];
        float a2 = dots[1 * 2112 + r * 33 + lane];
        float a3 = dots[2 * 2112 + r * 33 + lane];
        float a4 = dots[3 * 2112 + r * 33 + lane];

        float logit = -(a1 - 2.f * a2 + c2v);
        float S = clv + a3 - 2.f * a4 + c2v;

        float mx = logit;
#pragma unroll
        for (int o = 16; o; o >>= 1) mx = fmaxf(mx, __shfl_xor_sync(0xffffffffu, mx, o));
        float p = __expf(logit - mx);
        float ssum = wredsum(p);
        float pi = p / ssum + 1e-10f;

        piAcc += pi;
        gAcc += wredsum(pi * S);
    }
    __syncthreads();   // all dots reads done; RED overlay safe

    // ---- block partials ----
    redPi[wi * 32 + lane] = piAcc;
    if (lane == 0) redG[wi] = gAcc;
    __syncthreads();
    if (wi == 0) {
        float ps = 0.f;
#pragma unroll
        for (int i = 0; i < 16; ++i) ps += redPi[i * 32 + lane];
        g_piPart[blockIdx.x * 32 + lane] = ps;
        if (lane == 0) {
            float gsum = 0.f;
#pragma unroll
            for (int i = 0; i < 16; ++i) gsum += redG[i];
            g_gaussPart[blockIdx.x] = gsum;
        }
    }
    __syncthreads();

    // ---- last-block folded finalize ----
    if (t == 0) {
        __threadfence();
        unsigned int old = atomicAdd(&g_count, 1u);
        *flag = (old == NBLK - 1) ? 1 : 0;
    }
    __syncthreads();
    if (*flag) {
        if (t == 0) atomicExch(&g_count, 0u);
        __threadfence();
        if (t < NBLK) {
            float gg = g_gaussPart[t];
            gg = wredsum(gg);
            if (lane == 0) redG[wi] = gg;
        }
        {
            float ps = 0.f;
#pragma unroll
            for (int j = 0; j < 8; ++j)
                ps += g_piPart[(wi * 8 + j) * 32 + lane];
            redPi[wi * 32 + lane] = ps;
        }
        __syncthreads();
        if (t == 0) {
            float G = 0.f;
#pragma unroll
            for (int i = 0; i < 4; ++i) G += redG[i];
            out[out_size - 2] = 0.5f * G;
        }
        if (wi == 0) {
            float P = 0.f;
#pragma unroll
            for (int i = 0; i < 16; ++i) P += redPi[i * 32 + lane];
            float mp = P / (float)Bsz;
            float u = mp * logf(mp);
            u = wredsum(u);
            if (lane == 0) out[out_size - 1] = u / 32.0f;
        }
    }
}

// ---------------------------------------------------------------------------
extern "C" void kernel_launch(void* const* d_in, const int* in_sizes, int n_in,
                              void* d_out, int out_size) {
    const float* X    = (const float*)d_in[0];
    const float* EPS  = (const float*)d_in[1];
    const float* Wmu  = (const float*)d_in[2];
    const float* bmu  = (const float*)d_in[3];
    const float* Wsig = (const float*)d_in[4];
    const float* bsig = (const float*)d_in[5];
    const float* muc  = (const float*)d_in[6];
    const float* lsc  = (const float*)d_in[7];
    float* out = (float*)d_out;

    static bool attr_set = false;
    if (!attr_set) {
        cudaFuncSetAttribute(fused_kernel,
                             cudaFuncAttributeMaxDynamicSharedMemorySize, SMEM_BYTES);
        attr_set = true;
    }
    prep_kernel<<<69, 1024>>>(Wmu, Wsig, muc, lsc);
    fused_kernel<<<NBLK, THREADS, SMEM_BYTES>>>(X, EPS, bmu, bsig, out, out_size);
}

// round 17
// speedup vs baseline: 1.5006x; 1.2196x over previous
#include <cuda_runtime.h>
#include <math.h>
#include <stdint.h>

// Problem constants
#define Bsz 8192
#define TILE_B 64
#define NBLK 128
#define THREADS 512

// Shared memory (float words)
//  GEMM phase : AF [0,8192) (bf16x2)  W double buffer [8192,24576) (2 x 8192)
//               (W sliced per-warp: warp wi owns [wi*512, wi*512+512) of each buf)
//  overlay    : PA [0,32768)
//  disjoint   : TISC [32768,40960) TMCI [40960,49152)  (prefetched at start)
//  DOTS [49152,57600) ([4][64 r][33]);  RED overlays DOTS post-softmax
#define OFF_AF   0
#define OFF_W    8192
#define WBUF     8192
#define OFF_PA   0
#define OFF_TISC 32768
#define OFF_TMCI 40960
#define OFF_DOTS 49152
#define OFF_REDP 49152
#define OFF_REDG 49664
#define OFF_FLAG 49680
#define SMEM_FLOATS 57600
#define SMEM_BYTES (SMEM_FLOATS * 4)

// Precomputed fragment tables (block-invariant; written by prep each call)
// gBW (bf16x2): [ch 8][wi 16][ktc 2][ntgl 4][lane 32][reg 2]
__device__ uint32_t gBW[65536];
__device__ uint32_t gTisc[8192];   // tf32 isc frags: [kt 32][ntc 4][lane 32][reg 2]
__device__ uint32_t gTmci[8192];   // tf32 mci frags
__device__ float g_c2[32];
__device__ float g_clsc[32];
__device__ float g_gaussPart[NBLK];
__device__ float g_piPart[NBLK * 32];
__device__ unsigned int g_count;

// ---- helpers ----
__device__ __forceinline__ uint32_t f2tf32(float f) {
    uint32_t r; asm("cvt.rna.tf32.f32 %0,%1;" : "=r"(r) : "f"(f)); return r;
}
__device__ __forceinline__ uint32_t fpack_bf16(float lo, float hi) {
    uint32_t r; asm("cvt.rn.bf16x2.f32 %0,%1,%2;" : "=r"(r) : "f"(hi), "f"(lo));
    return r;
}
__device__ __forceinline__ float wredsum(float v) {
#pragma unroll
    for (int o = 16; o; o >>= 1) v += __shfl_xor_sync(0xffffffffu, v, o);
    return v;
}
__device__ __forceinline__ void mma_tf32(float* d, const uint32_t* a,
                                         uint32_t b0, uint32_t b1) {
    asm volatile(
        "mma.sync.aligned.m16n8k8.row.col.f32.tf32.tf32.f32 "
        "{%0,%1,%2,%3},{%4,%5,%6,%7},{%8,%9},{%0,%1,%2,%3};"
        : "+f"(d[0]), "+f"(d[1]), "+f"(d[2]), "+f"(d[3])
        : "r"(a[0]), "r"(a[1]), "r"(a[2]), "r"(a[3]), "r"(b0), "r"(b1));
}
__device__ __forceinline__ void mma_bf16(float* d, const uint32_t* a,
                                         uint32_t b0, uint32_t b1) {
    asm volatile(
        "mma.sync.aligned.m16n8k16.row.col.f32.bf16.bf16.f32 "
        "{%0,%1,%2,%3},{%4,%5,%6,%7},{%8,%9},{%0,%1,%2,%3};"
        : "+f"(d[0]), "+f"(d[1]), "+f"(d[2]), "+f"(d[3])
        : "r"(a[0]), "r"(a[1]), "r"(a[2]), "r"(a[3]), "r"(b0), "r"(b1));
}
#define CP16(dst_u32, src_ptr) \
    asm volatile("cp.async.cg.shared.global [%0],[%1],16;" :: "r"(dst_u32), "l"(src_ptr))
#define CP_COMMIT() asm volatile("cp.async.commit_group;")
#define CP_WAIT(n)  asm volatile("cp.async.wait_group %0;" :: "n"(n))

// ---------------------------------------------------------------------------
// prep: W -> bf16x2 fragments (warp-sliced); cluster tables -> tf32 fragments
// ---------------------------------------------------------------------------
__global__ void __launch_bounds__(1024)
prep_kernel(const float* __restrict__ Wmu, const float* __restrict__ Wsig,
            const float* __restrict__ muc, const float* __restrict__ lsc) {
    int b = blockIdx.x, t = threadIdx.x;
    if (b < 32) {
        int idx = b * 1024 + t;              // (kt16 * 64 + ntg)*32 + lane
        int lane = idx & 31;
        int g = lane >> 2, tg = lane & 3;
        int ntg = (idx >> 5) & 63, kt = idx >> 11;   // kt 0..15 (k16 steps)
        const float* W = (ntg & 32) ? Wsig : Wmu;
        int e = (ntg & 31) * 8 + g;
        int d0 = kt * 16 + 2 * tg;
        int d1 = kt * 16 + 8 + 2 * tg;
        uint2 vv;
        vv.x = fpack_bf16(W[e * 256 + d0], W[e * 256 + d0 + 1]);
        vv.y = fpack_bf16(W[e * 256 + d1], W[e * 256 + d1 + 1]);
        // warp-sliced remap: ch = kt>>1, ktc = kt&1
        int ch = kt >> 1, ktc = kt & 1;
        int wiw = (ntg & 31) >> 1;
        int ntgl = ((ntg >> 5) << 1) | (ntg & 1);
        int nidx = (((ch * 16 + wiw) * 2 + ktc) * 4 + ntgl) * 32 + lane;
        *(uint2*)&gBW[nidx * 2] = vv;
    } else if (b < 36) {
        int idx = (b - 32) * 1024 + t;       // (kt8 * 4 + ntc)*32 + lane
        int lane = idx & 31;
        int g = lane >> 2, tg = lane & 3;
        int ntc = (idx >> 5) & 3, kt = idx >> 7;
        int k = ntc * 8 + g;
        int d = kt * 8 + tg;
        float l0 = lsc[k * 256 + d], l1 = lsc[k * 256 + d + 4];
        float i0 = expf(-l0), i1 = expf(-l1);
        uint2 iv = {f2tf32(i0), f2tf32(i1)};
        uint2 mv = {f2tf32(muc[k * 256 + d] * i0), f2tf32(muc[k * 256 + d + 4] * i1)};
        *(uint2*)&gTisc[idx * 2] = iv;
        *(uint2*)&gTmci[idx * 2] = mv;
    } else {
        int k = t >> 5, lane = t & 31;       // warp per cluster
        float c2 = 0.f, cl = 0.f;
#pragma unroll
        for (int j = 0; j < 8; ++j) {
            int d = j * 32 + lane;
            float l = lsc[k * 256 + d];
            float iv = expf(-l);
            float mc = muc[k * 256 + d];
            c2 = fmaf(mc * mc, iv, c2);
            cl += l;
        }
        c2 = wredsum(c2);
        cl = wredsum(cl);
        if (lane == 0) { g_c2[k] = c2; g_clsc[k] = cl; }
    }
}

// ---------------------------------------------------------------------------
__global__ void __launch_bounds__(THREADS)
fused_kernel(const float* __restrict__ X, const float* __restrict__ EPS,
             const float* __restrict__ bmu, const float* __restrict__ bsig,
             float* __restrict__ out, int out_size) {
    extern __shared__ float sm[];
    uint32_t* smU = (uint32_t*)sm;
    float* dots  = sm + OFF_DOTS;
    float* redPi = sm + OFF_REDP;
    float* redG  = sm + OFF_REDG;
    int*   flag  = (int*)(sm + OFF_FLAG);
    const uint32_t smBase = (uint32_t)__cvta_generic_to_shared(sm);

    const int t = threadIdx.x;
    const int b0 = blockIdx.x * TILE_B;
    const int wi = t >> 5, lane = t & 31;
    const int g = lane >> 2, tg = lane & 3;
    const int cb = wi * 16;

    // warp-private W pipeline pointers (2048 B slice per warp per chunk)
    const char* wsrc = (const char*)gBW + (size_t)wi * 2048;    // + ch*32768
    const int laneOff = lane * 16;

    // ---- issue warp's slice of W chunk 0 (group 0) ----
    {
        uint32_t dst = smBase + (OFF_W + wi * 512) * 4;
#pragma unroll
        for (int p = 0; p < 4; ++p)
            CP16(dst + p * 512 + laneOff, wsrc + p * 512 + laneOff);
        CP_COMMIT();
    }
    // ---- prefetch cluster tables (group 1; region disjoint from GEMM) ----
    {
        uint32_t dI = smBase + OFF_TISC * 4;
        uint32_t dM = smBase + OFF_TMCI * 4;
#pragma unroll
        for (int p = 0; p < 4; ++p) {
            int off = (p * THREADS + t) * 16;
            CP16(dI + off, (const char*)gTisc + off);
            CP16(dM + off, (const char*)gTmci + off);
        }
        CP_COMMIT();
    }

    // ============ X -> A fragments (bf16x2), 64 rows ============
#pragma unroll
    for (int p = 0; p < 16; ++p) {
        int i = p * THREADS + t;
        int r = i >> 7, d2 = i & 127;
        int d = d2 * 2;
        float2 xv = *(const float2*)&X[(b0 + r) * 256 + d];
        uint32_t v = fpack_bf16(xv.x, xv.y);
        int mt = r >> 4, rl = r & 15, gg = rl & 7, hi = rl >> 3;
        int kt = d >> 4, dc = d & 15, kh = dc >> 3, tgx = (dc & 7) >> 1;
        smU[OFF_AF + (((kt * 4 + mt) * 32) + gg * 4 + tgx) * 4 + (hi + 2 * kh)] = v;
    }

    float acc[4][2][2][4];   // [mt][m][j][creg]
#pragma unroll
    for (int a = 0; a < 4; ++a)
#pragma unroll
        for (int b = 0; b < 2; ++b)
#pragma unroll
            for (int c = 0; c < 2; ++c)
#pragma unroll
                for (int q = 0; q < 4; ++q) acc[a][b][c][q] = 0.f;

    __syncthreads();   // AF visible; mainloop is barrier-free

    // ============ main GEMM: bf16 k16, warp-private double buffer ==========
#pragma unroll 1
    for (int ch = 0; ch < 8; ++ch) {
        if (ch < 7) {
            uint32_t dst = smBase + (OFF_W + ((ch + 1) & 1) * WBUF + wi * 512) * 4;
            const char* src = wsrc + (size_t)(ch + 1) * 32768;
#pragma unroll
            for (int p = 0; p < 4; ++p)
                CP16(dst + p * 512 + laneOff, src + p * 512 + laneOff);
            CP_COMMIT();
            CP_WAIT(1);
        } else {
            CP_WAIT(0);
        }
        __syncwarp();   // cross-lane visibility of this warp's staged slice

        const uint32_t* ws = smU + OFF_W + (ch & 1) * WBUF + wi * 512;
#pragma unroll
        for (int ktc = 0; ktc < 2; ++ktc) {
            int kt = ch * 2 + ktc;
            uint32_t a[4][4];
#pragma unroll
            for (int mt = 0; mt < 4; ++mt)
                *(uint4*)a[mt] = *(const uint4*)&smU[OFF_AF + ((kt * 4 + mt) * 32 + lane) * 4];
            uint2 bv[2][2];
#pragma unroll
            for (int m = 0; m < 2; ++m)
#pragma unroll
                for (int j = 0; j < 2; ++j)
                    bv[m][j] = *(const uint2*)&ws[((ktc * 4 + m * 2 + j) * 32 + lane) * 2];
#pragma unroll
            for (int m = 0; m < 2; ++m)
#pragma unroll
                for (int j = 0; j < 2; ++j)
#pragma unroll
                    for (int mt = 0; mt < 4; ++mt)
                        mma_bf16(acc[mt][m][j], a[mt], bv[m][j].x, bv[m][j].y);
        }
    }
    __syncthreads();   // all warps done with AF/W; PA overlay safe

    // ============ Phase B pass 1: z out + PA = [z^2 ; q] ============
#pragma unroll
    for (int mt = 0; mt < 4; ++mt) {
#pragma unroll
        for (int j = 0; j < 2; ++j) {
            int e2 = cb + j * 8 + 2 * tg;
            float2 bm = *(const float2*)&bmu[e2];
            float2 bs = *(const float2*)&bsig[e2];
            int ktw = wi * 2 + j;
#pragma unroll
            for (int hi = 0; hi < 2; ++hi) {
                int r = mt * 16 + g + 8 * hi;
                int ci = hi * 2;
                float mu0 = acc[mt][0][j][ci + 0] + bm.x;
                float mu1 = acc[mt][0][j][ci + 1] + bm.y;
                float ls0 = acc[mt][1][j][ci + 0] + bs.x;
                float ls1 = acc[mt][1][j][ci + 1] + bs.y;
                float ez0 = __expf(ls0), ez1 = __expf(ls1);
                float2 ep = *(const float2*)&EPS[(b0 + r) * 256 + e2];
                float z0 = fmaf(sqrtf(ez0), ep.x, mu0);
                float z1 = fmaf(sqrtf(ez1), ep.y, mu1);
                float2 zv = {z0, z1};
                *(float2*)&out[(b0 + r) * 256 + e2] = zv;
                float q0 = fmaf(mu0, mu0, ez0);
                float q1 = fmaf(mu1, mu1, ez1);
#pragma unroll
                for (int par = 0; par < 2; ++par) {
                    int dd = 2 * tg + par;
                    int kh = dd >> 2, tgp = dd & 3;
                    int reg = hi + 2 * kh;
                    int lanep = g * 4 + tgp;
                    float zz = par ? z1 : z0;
                    float qq = par ? q1 : q0;
                    smU[OFF_PA + ((ktw * 8 + mt) * 4 + reg) * 32 + lanep]     = f2tf32(zz * zz);
                    smU[OFF_PA + ((ktw * 8 + mt + 4) * 4 + reg) * 32 + lanep] = f2tf32(qq);
                }
            }
        }
    }
    __syncthreads();   // PA ready (tables arrived during GEMM)

    const int mtc = wi >> 1;          // 0..7 -> 16-row tile
    const int ntch = wi & 1;          // k half

    // ============ Phase C GEMM 1: [z^2;q] @ isc -> a1, a3 (tf32) ============
    {
        float dA[2][4];
#pragma unroll
        for (int s = 0; s < 2; ++s)
#pragma unroll
            for (int q = 0; q < 4; ++q) dA[s][q] = 0.f;
#pragma unroll 4
        for (int kt = 0; kt < 32; ++kt) {
            uint32_t af[4];
#pragma unroll
            for (int rr = 0; rr < 4; ++rr)
                af[rr] = smU[OFF_PA + ((kt * 8 + mtc) * 4 + rr) * 32 + lane];
#pragma unroll
            for (int s = 0; s < 2; ++s) {
                int ntc = ntch * 2 + s;
                uint2 iv = *(const uint2*)&smU[OFF_TISC + ((kt * 4 + ntc) * 32 + lane) * 2];
                mma_tf32(dA[s], af, iv.x, iv.y);
            }
        }
        int dot = (mtc < 4) ? 0 : 2;
        int rloc = (mtc & 3) * 16 + g;
#pragma unroll
        for (int s = 0; s < 2; ++s)
#pragma unroll
            for (int hi = 0; hi < 2; ++hi)
#pragma unroll
                for (int par = 0; par < 2; ++par) {
                    int r = rloc + 8 * hi;
                    int k = ntch * 16 + s * 8 + 2 * tg + par;
                    dots[dot * 2112 + r * 33 + k] = dA[s][hi * 2 + par];
                }
    }
    __syncthreads();   // GEMM1 PA reads done; PA rebuild safe

    // ============ Phase B pass 2: PA = [z ; mu] (recomputed) ============
#pragma unroll
    for (int mt = 0; mt < 4; ++mt) {
#pragma unroll
        for (int j = 0; j < 2; ++j) {
            int e2 = cb + j * 8 + 2 * tg;
            float2 bm = *(const float2*)&bmu[e2];
            float2 bs = *(const float2*)&bsig[e2];
            int ktw = wi * 2 + j;
#pragma unroll
            for (int hi = 0; hi < 2; ++hi) {
                int r = mt * 16 + g + 8 * hi;
                int ci = hi * 2;
                float mu0 = acc[mt][0][j][ci + 0] + bm.x;
                float mu1 = acc[mt][0][j][ci + 1] + bm.y;
                float ls0 = acc[mt][1][j][ci + 0] + bs.x;
                float ls1 = acc[mt][1][j][ci + 1] + bs.y;
                float2 ep = *(const float2*)&EPS[(b0 + r) * 256 + e2];
                float z0 = fmaf(sqrtf(__expf(ls0)), ep.x, mu0);
                float z1 = fmaf(sqrtf(__expf(ls1)), ep.y, mu1);
#pragma unroll
                for (int par = 0; par < 2; ++par) {
                    int dd = 2 * tg + par;
                    int kh = dd >> 2, tgp = dd & 3;
                    int reg = hi + 2 * kh;
                    int lanep = g * 4 + tgp;
                    float zz = par ? z1 : z0;
                    float mm = par ? mu1 : mu0;
                    smU[OFF_PA + ((ktw * 8 + mt) * 4 + reg) * 32 + lanep]     = f2tf32(zz);
                    smU[OFF_PA + ((ktw * 8 + mt + 4) * 4 + reg) * 32 + lanep] = f2tf32(mm);
                }
            }
        }
    }
    __syncthreads();

    // ============ Phase C GEMM 2: [z;mu] @ mci -> a2, a4 (tf32) ============
    {
        float dA[2][4];
#pragma unroll
        for (int s = 0; s < 2; ++s)
#pragma unroll
            for (int q = 0; q < 4; ++q) dA[s][q] = 0.f;
#pragma unroll 4
        for (int kt = 0; kt < 32; ++kt) {
            uint32_t af[4];
#pragma unroll
            for (int rr = 0; rr < 4; ++rr)
                af[rr] = smU[OFF_PA + ((kt * 8 + mtc) * 4 + rr) * 32 + lane];
#pragma unroll
            for (int s = 0; s < 2; ++s) {
                int ntc = ntch * 2 + s;
                uint2 mv = *(const uint2*)&smU[OFF_TMCI + ((kt * 4 + ntc) * 32 + lane) * 2];
                mma_tf32(dA[s], af, mv.x, mv.y);
            }
        }
        int dot = (mtc < 4) ? 1 : 3;
        int rloc = (mtc & 3) * 16 + g;
#pragma unroll
        for (int s = 0; s < 2; ++s)
#pragma unroll
            for (int hi = 0; hi < 2; ++hi)
#pragma unroll
                for (int par = 0; par < 2; ++par) {
                    int r = rloc + 8 * hi;
                    int k = ntch * 16 + s * 8 + 2 * tg + par;
                    dots[dot * 2112 + r * 33 + k] = dA[s][hi * 2 + par];
                }
    }
    __syncthreads();

    // ============ softmax + loss partials: warp per 4 rows, lane == k ======
    float c2v = g_c2[lane], clv = g_clsc[lane];
    float piAcc = 0.f, gAcc = 0.f;
#pragma unroll
    for (int rr = 0; rr < 4; ++rr) {
        int r = wi * 4 + rr;
        float a1 = dots[0 * 2112 + r * 33 + lane];
        float a2 = dots[1 * 2112 + r * 33 + lane];
        float a3 = dots[2 * 2112 + r * 33 + lane];
        float a4 = dots[3 * 2112 + r * 33 + lane];

        float logit = -(a1 - 2.f * a2 + c2v);
        float S = clv + a3 - 2.f * a4 + c2v;

        float mx = logit;
#pragma unroll
        for (int o = 16; o; o >>= 1) mx = fmaxf(mx, __shfl_xor_sync(0xffffffffu, mx, o));
        float p = __expf(logit - mx);
        float ssum = wredsum(p);
        float pi = p / ssum + 1e-10f;

        piAcc += pi;
        gAcc += wredsum(pi * S);
    }
    __syncthreads();   // all dots reads done; RED overlay safe

    // ---- block partials ----
    redPi[wi * 32 + lane] = piAcc;
    if (lane == 0) redG[wi] = gAcc;
    __syncthreads();
    if (wi == 0) {
        float ps = 0.f;
#pragma unroll
        for (int i = 0; i < 16; ++i) ps += redPi[i * 32 + lane];
        g_piPart[blockIdx.x * 32 + lane] = ps;
        if (lane == 0) {
            float gsum = 0.f;
#pragma unroll
            for (int i = 0; i < 16; ++i) gsum += redG[i];
            g_gaussPart[blockIdx.x] = gsum;
        }
    }
    __syncthreads();

    // ---- last-block folded finalize ----
    if (t == 0) {
        __threadfence();
        unsigned int old = atomicAdd(&g_count, 1u);
        *flag = (old == NBLK - 1) ? 1 : 0;
    }
    __syncthreads();
    if (*flag) {
        if (t == 0) atomicExch(&g_count, 0u);
        __threadfence();
        if (t < NBLK) {
            float gg = g_gaussPart[t];
            gg = wredsum(gg);
            if (lane == 0) redG[wi] = gg;
        }
        {
            float ps = 0.f;
#pragma unroll
            for (int j = 0; j < 8; ++j)
                ps += g_piPart[(wi * 8 + j) * 32 + lane];
            redPi[wi * 32 + lane] = ps;
        }
        __syncthreads();
        if (t == 0) {
            float G = 0.f;
#pragma unroll
            for (int i = 0; i < 4; ++i) G += redG[i];
            out[out_size - 2] = 0.5f * G;
        }
        if (wi == 0) {
            float P = 0.f;
#pragma unroll
            for (int i = 0; i < 16; ++i) P += redPi[i * 32 + lane];
            float mp = P / (float)Bsz;
            float u = mp * logf(mp);
            u = wredsum(u);
            if (lane == 0) out[out_size - 1] = u / 32.0f;
        }
    }
}

// ---------------------------------------------------------------------------
extern "C" void kernel_launch(void* const* d_in, const int* in_sizes, int n_in,
                              void* d_out, int out_size) {
    const float* X    = (const float*)d_in[0];
    const float* EPS  = (const float*)d_in[1];
    const float* Wmu  = (const float*)d_in[2];
    const float* bmu  = (const float*)d_in[3];
    const float* Wsig = (const float*)d_in[4];
    const float* bsig = (const float*)d_in[5];
    const float* muc  = (const float*)d_in[6];
    const float* lsc  = (const float*)d_in[7];
    float* out = (float*)d_out;

    static bool attr_set = false;
    if (!attr_set) {
        cudaFuncSetAttribute(fused_kernel,
                             cudaFuncAttributeMaxDynamicSharedMemorySize, SMEM_BYTES);
        attr_set = true;
    }
    prep_kernel<<<37, 1024>>>(Wmu, Wsig, muc, lsc);
    fused_kernel<<<NBLK, THREADS, SMEM_BYTES>>>(X, EPS, bmu, bsig, out, out_size);
}